// round 6
// baseline (speedup 1.0000x reference)
#include <cuda_runtime.h>
#include <cstdint>

#define CIN 16
#define COUT 32
#define K2 9
#define MAXN 2000000
#define NW 6            // warps per block
#define BT 192          // threads per block
#define VPW 64          // voxels per warp
#define VPB (NW * VPW)  // 384 voxels per block
#define S1T 66          // conv1 tile row stride (floats)
#define S2T 66          // conv2 tile row stride (floats)

// Intermediate h1 = relu(conv1(x)) : [N, 32] fp32 (256 MB scratch).
__device__ float g_h1[(size_t)MAXN * COUT];

typedef unsigned long long ull;

__device__ __forceinline__ ull pack2(float a, float b) {
    ull r; asm("mov.b64 %0, {%1, %2};" : "=l"(r) : "f"(a), "f"(b)); return r;
}
__device__ __forceinline__ float2 unpack2(ull v) {
    float2 f; asm("mov.b64 {%0, %1}, %2;" : "=f"(f.x), "=f"(f.y) : "l"(v)); return f;
}
__device__ __forceinline__ ull fma2(ull a, ull b, ull c) {
    ull d; asm("fma.rn.f32x2 %0, %1, %2, %3;" : "=l"(d) : "l"(a), "l"(b), "l"(c)); return d;
}

// Thread tile: tx = lane&3 -> couts [8tx, 8tx+8); ty = lane>>2 -> voxels [8ty, 8ty+8)
// acc[j][p]: f32x2 over voxel pair (8ty+2p, 8ty+2p+1), cout 8tx+j.

// =====================================================================
// conv1: h1 = relu( sum_k mask*x[idx] @ W1[k] + b1 )
// =====================================================================
__global__ __launch_bounds__(BT, 2)
void conv1_kernel(const float* __restrict__ x,
                  const float* __restrict__ W1,
                  const float* __restrict__ b1,
                  const int* __restrict__ nbr_idx,
                  const unsigned int* __restrict__ nbr_mask,
                  int n) {
    extern __shared__ float sm[];
    float* Wf = sm;                        // K2*CIN*COUT = 4608
    float* bf = Wf + K2 * CIN * COUT;      // 32
    float* tiles = bf + COUT;              // NW * CIN * S1T

    const int t = threadIdx.x, lane = t & 31, w = t >> 5;
    const int tx = lane & 3, ty = lane >> 2;
    const int q4 = lane & 3, r8 = lane >> 2;     // staging: chunk q4, row-group r8
    float* xt = tiles + w * (CIN * S1T);
    const int v0w = blockIdx.x * VPB + w * VPW;

    float4 st[8];
    auto load_tap = [&](int k) {
#pragma unroll
        for (int i = 0; i < 8; i++) {
            int v = v0w + r8 + 8 * i;
            float4 g = make_float4(0.f, 0.f, 0.f, 0.f);
            if (v < n) {
                size_t off = (size_t)k * n + v;
                if (nbr_mask[off])
                    g = __ldg((const float4*)(x + (size_t)nbr_idx[off] * CIN + 4 * q4));
            }
            st[i] = g;
        }
    };
    auto sts_tap = [&]() {     // conflict-free: bank = (8q4 + r8 + 2cc) mod 32
#pragma unroll
        for (int i = 0; i < 8; i++) {
            int vl = r8 + 8 * i, ch = 4 * q4;
            xt[(ch + 0) * S1T + vl] = st[i].x;
            xt[(ch + 1) * S1T + vl] = st[i].y;
            xt[(ch + 2) * S1T + vl] = st[i].z;
            xt[(ch + 3) * S1T + vl] = st[i].w;
        }
    };

    load_tap(0);
    for (int i = t; i < K2 * CIN * COUT; i += BT) Wf[i] = W1[i];
    if (t < COUT) bf[t] = b1[t];
    __syncthreads();

    ull acc[8][4];
#pragma unroll
    for (int j = 0; j < 8; j++) {
        float bv = bf[8 * tx + j];
        ull bb = pack2(bv, bv);
#pragma unroll
        for (int p = 0; p < 4; p++) acc[j][p] = bb;
    }

    sts_tap();
    __syncwarp();

    for (int k = 0; k < K2; k++) {
        if (k < K2 - 1) load_tap(k + 1);
        const float* wk = Wf + k * (CIN * COUT);
#pragma unroll
        for (int c = 0; c < CIN; c++) {
            float4 wa = *(const float4*)(wk + c * COUT + 8 * tx);
            float4 wb = *(const float4*)(wk + c * COUT + 8 * tx + 4);
            ull hp[4];
#pragma unroll
            for (int p = 0; p < 4; p++)
                hp[p] = *(const ull*)(xt + c * S1T + 8 * ty + 2 * p);
            float wv[8] = {wa.x, wa.y, wa.z, wa.w, wb.x, wb.y, wb.z, wb.w};
#pragma unroll
            for (int j = 0; j < 8; j++) {
                ull wd = pack2(wv[j], wv[j]);
#pragma unroll
                for (int p = 0; p < 4; p++) acc[j][p] = fma2(hp[p], wd, acc[j][p]);
            }
        }
        __syncwarp();
        if (k < K2 - 1) sts_tap();
        __syncwarp();
    }

    // epilogue: relu -> g_h1
#pragma unroll
    for (int p = 0; p < 4; p++) {
#pragma unroll
        for (int d = 0; d < 2; d++) {
            int v = v0w + 8 * ty + 2 * p + d;
            if (v < n) {
                float o[8];
#pragma unroll
                for (int j = 0; j < 8; j++) {
                    float2 f = unpack2(acc[j][p]);
                    o[j] = fmaxf(d ? f.y : f.x, 0.f);
                }
                float* op = g_h1 + (size_t)v * COUT + 8 * tx;
                *(float4*)(op)     = make_float4(o[0], o[1], o[2], o[3]);
                *(float4*)(op + 4) = make_float4(o[4], o[5], o[6], o[7]);
            }
        }
    }
}

// =====================================================================
// conv2 + residual: out = relu( sum_k mask*h1[idx] @ W2[k] + b2 + x @ Wp + bp )
// =====================================================================
__global__ __launch_bounds__(BT, 2)
void conv2_kernel(const float* __restrict__ x,
                  const float* __restrict__ W2,
                  const float* __restrict__ b2,
                  const float* __restrict__ Wp,
                  const float* __restrict__ bp,
                  const int* __restrict__ nbr_idx,
                  const unsigned int* __restrict__ nbr_mask,
                  float* __restrict__ out,
                  int n) {
    extern __shared__ float sm[];
    float* Wf  = sm;                            // 9216
    float* Wpf = Wf + K2 * COUT * COUT;         // 512
    float* bf  = Wpf + CIN * COUT;              // 32
    float* tiles = bf + COUT;                   // NW * COUT * S2T

    const int t = threadIdx.x, lane = t & 31, w = t >> 5;
    const int tx = lane & 3, ty = lane >> 2;
    const int q8 = lane & 7, r4 = lane >> 3;    // tap staging (8 chunks/row)
    const int q4 = lane & 3, r8 = lane >> 2;    // proj staging (4 chunks/row)
    float* xt = tiles + w * (COUT * S2T);
    const int v0w = blockIdx.x * VPB + w * VPW;

    float4 stA[8], stB[8];

    // tap staging: chunk h covers voxels [h*32, h*32+32): i local 0..7, vox = r4 + 4*(8h+i)
    auto load_half = [&](int k, int h, float4* st) {
#pragma unroll
        for (int i = 0; i < 8; i++) {
            int v = v0w + r4 + 4 * (8 * h + i);
            float4 g = make_float4(0.f, 0.f, 0.f, 0.f);
            if (v < n) {
                size_t off = (size_t)k * n + v;
                if (nbr_mask[off])
                    g = __ldg((const float4*)(g_h1 + (size_t)nbr_idx[off] * COUT + 4 * q8));
            }
            st[i] = g;
        }
    };
    auto sts_half = [&](int h, const float4* st) {
#pragma unroll
        for (int i = 0; i < 8; i++) {
            int vl = r4 + 4 * (8 * h + i), ch = 4 * q8;
            xt[(ch + 0) * S2T + vl] = st[i].x;
            xt[(ch + 1) * S2T + vl] = st[i].y;
            xt[(ch + 2) * S2T + vl] = st[i].z;
            xt[(ch + 3) * S2T + vl] = st[i].w;
        }
    };
    auto load_proj = [&]() {
#pragma unroll
        for (int i = 0; i < 8; i++) {
            int v = v0w + r8 + 8 * i;
            float4 g = make_float4(0.f, 0.f, 0.f, 0.f);
            if (v < n) g = __ldg((const float4*)(x + (size_t)v * CIN + 4 * q4));
            stA[i] = g;
        }
    };
    auto sts_proj = [&]() {
#pragma unroll
        for (int i = 0; i < 8; i++) {
            int vl = r8 + 8 * i, ch = 4 * q4;
            xt[(ch + 0) * S2T + vl] = stA[i].x;
            xt[(ch + 1) * S2T + vl] = stA[i].y;
            xt[(ch + 2) * S2T + vl] = stA[i].z;
            xt[(ch + 3) * S2T + vl] = stA[i].w;
        }
    };

    load_proj();
    for (int i = t; i < K2 * COUT * COUT; i += BT) Wf[i] = W2[i];
    for (int i = t; i < CIN * COUT; i += BT) Wpf[i] = Wp[i];
    if (t < COUT) bf[t] = b2[t] + bp[t];
    __syncthreads();

    ull acc[8][4];
#pragma unroll
    for (int j = 0; j < 8; j++) {
        float bv = bf[8 * tx + j];
        ull bb = pack2(bv, bv);
#pragma unroll
        for (int p = 0; p < 4; p++) acc[j][p] = bb;
    }

    sts_proj();
    __syncwarp();
    load_half(0, 0, stA);      // tap-0 first half in flight over proj compute

    // residual projection: channels 0..15 of the tile
#pragma unroll
    for (int c = 0; c < CIN; c++) {
        float4 wa = *(const float4*)(Wpf + c * COUT + 8 * tx);
        float4 wb = *(const float4*)(Wpf + c * COUT + 8 * tx + 4);
        ull hp[4];
#pragma unroll
        for (int p = 0; p < 4; p++)
            hp[p] = *(const ull*)(xt + c * S2T + 8 * ty + 2 * p);
        float wv[8] = {wa.x, wa.y, wa.z, wa.w, wb.x, wb.y, wb.z, wb.w};
#pragma unroll
        for (int j = 0; j < 8; j++) {
            ull wd = pack2(wv[j], wv[j]);
#pragma unroll
            for (int p = 0; p < 4; p++) acc[j][p] = fma2(hp[p], wd, acc[j][p]);
        }
    }
    load_half(0, 1, stB);
    __syncwarp();
    sts_half(0, stA); sts_half(1, stB);
    __syncwarp();

    for (int k = 0; k < K2; k++) {
        const float* wk = Wf + k * (COUT * COUT);
        if (k < K2 - 1) load_half(k + 1, 0, stA);
#pragma unroll
        for (int c = 0; c < COUT; c++) {
            if (c == COUT / 2 && k < K2 - 1) load_half(k + 1, 1, stB);
            float4 wa = *(const float4*)(wk + c * COUT + 8 * tx);
            float4 wb = *(const float4*)(wk + c * COUT + 8 * tx + 4);
            ull hp[4];
#pragma unroll
            for (int p = 0; p < 4; p++)
                hp[p] = *(const ull*)(xt + c * S2T + 8 * ty + 2 * p);
            float wv[8] = {wa.x, wa.y, wa.z, wa.w, wb.x, wb.y, wb.z, wb.w};
#pragma unroll
            for (int j = 0; j < 8; j++) {
                ull wd = pack2(wv[j], wv[j]);
#pragma unroll
                for (int p = 0; p < 4; p++) acc[j][p] = fma2(hp[p], wd, acc[j][p]);
            }
        }
        __syncwarp();
        if (k < K2 - 1) { sts_half(0, stA); sts_half(1, stB); }
        __syncwarp();
    }

    // epilogue: relu -> out
#pragma unroll
    for (int p = 0; p < 4; p++) {
#pragma unroll
        for (int d = 0; d < 2; d++) {
            int v = v0w + 8 * ty + 2 * p + d;
            if (v < n) {
                float o[8];
#pragma unroll
                for (int j = 0; j < 8; j++) {
                    float2 f = unpack2(acc[j][p]);
                    o[j] = fmaxf(d ? f.y : f.x, 0.f);
                }
                float* op = out + (size_t)v * COUT + 8 * tx;
                *(float4*)(op)     = make_float4(o[0], o[1], o[2], o[3]);
                *(float4*)(op + 4) = make_float4(o[4], o[5], o[6], o[7]);
            }
        }
    }
}

// =====================================================================
// Launch.  Input order: x, W1, b1, W2, b2, Wp, bp, nbr_idx, nbr_mask
// =====================================================================
extern "C" void kernel_launch(void* const* d_in, const int* in_sizes, int n_in,
                              void* d_out, int out_size) {
    const float* x  = (const float*)d_in[0];
    const float* W1 = (const float*)d_in[1];
    const float* b1 = (const float*)d_in[2];
    const float* W2 = (const float*)d_in[3];
    const float* b2 = (const float*)d_in[4];
    const float* Wp = (const float*)d_in[5];
    const float* bp = (const float*)d_in[6];
    const int* nbr_idx = (const int*)d_in[7];
    const unsigned int* nbr_mask = (const unsigned int*)d_in[8];
    float* out = (float*)d_out;

    int n = in_sizes[0] / CIN;
    if (n > MAXN) n = MAXN;

    const int smem1 = (K2 * CIN * COUT + COUT + NW * CIN * S1T) * 4;
    const int smem2 = (K2 * COUT * COUT + CIN * COUT + COUT + NW * COUT * S2T) * 4;

    cudaFuncSetAttribute(conv1_kernel, cudaFuncAttributeMaxDynamicSharedMemorySize, smem1);
    cudaFuncSetAttribute(conv2_kernel, cudaFuncAttributeMaxDynamicSharedMemorySize, smem2);

    int blocks = (n + VPB - 1) / VPB;
    conv1_kernel<<<blocks, BT, smem1>>>(x, W1, b1, nbr_idx, nbr_mask, n);
    conv2_kernel<<<blocks, BT, smem2>>>(x, W2, b2, Wp, bp, nbr_idx, nbr_mask, out, n);
}